// round 2
// baseline (speedup 1.0000x reference)
#include <cuda_runtime.h>

// Erosion2D: out[b,y,x,c] = min_{dy,dx in [0,4)} x[y+dy-1, x+dx-1, c] - w[3-dy, 3-dx, c]
// No-smem register-walk version: each thread owns (output row, channel pair) and
// walks XW columns, keeping a 3-deep ring of per-column partial mins in registers.
// Subtractions done as packed add.rn.f32x2 with pre-negated weights.

typedef unsigned long long ull;
#define BIGF 1e30f

constexpr int B = 8, H = 512, W = 512, C = 32;
constexpr int TY = 16;              // output rows per block
constexpr int XW = 128;             // output columns walked per thread
constexpr int THREADS = TY * 16;    // 16 channel-pairs
constexpr int ROWSTR = W * C;       // floats between consecutive image rows

// 1e30f bit pattern duplicated into both lanes
constexpr ull BIG2 = 0x7149F2CA7149F2CAull;

__device__ __forceinline__ ull addx2(ull a, ull b) {
    ull r; asm("add.rn.f32x2 %0, %1, %2;" : "=l"(r) : "l"(a), "l"(b)); return r;
}
__device__ __forceinline__ float2 u2f(ull a) {
    float2 f; asm("mov.b64 {%0, %1}, %2;" : "=f"(f.x), "=f"(f.y) : "l"(a)); return f;
}
__device__ __forceinline__ ull f2u(float x, float y) {
    ull r; asm("mov.b64 %0, {%1, %2};" : "=l"(r) : "f"(x), "f"(y)); return r;
}

// column pass: cd[d] = min_k (r_k + nw[d][k]),  nw = -w[3-k][3-d]
__device__ __forceinline__ void colpass(ull r0, ull r1, ull r2, ull r3,
                                        const ull (&nw)[4][4], float2 (&cd)[4]) {
#pragma unroll
    for (int d = 0; d < 4; d++) {
        float2 a0 = u2f(addx2(r0, nw[d][0]));
        float2 a1 = u2f(addx2(r1, nw[d][1]));
        float2 a2 = u2f(addx2(r2, nw[d][2]));
        float2 a3 = u2f(addx2(r3, nw[d][3]));
        cd[d].x = fminf(fminf(a0.x, a1.x), fminf(a2.x, a3.x));
        cd[d].y = fminf(fminf(a0.y, a1.y), fminf(a2.y, a3.y));
    }
}

template <bool EDGE>
__device__ __forceinline__ void loadrows(const float* __restrict__ p,
                                         bool v0, bool v1, bool v2, bool v3,
                                         ull& r0, ull& r1, ull& r2, ull& r3) {
    if (EDGE) {
        r0 = v0 ? *(const ull*)(p)              : BIG2;
        r1 = v1 ? *(const ull*)(p + ROWSTR)     : BIG2;
        r2 = v2 ? *(const ull*)(p + 2 * ROWSTR) : BIG2;
        r3 = v3 ? *(const ull*)(p + 3 * ROWSTR) : BIG2;
    } else {
        r0 = *(const ull*)(p);
        r1 = *(const ull*)(p + ROWSTR);
        r2 = *(const ull*)(p + 2 * ROWSTR);
        r3 = *(const ull*)(p + 3 * ROWSTR);
    }
}

template <bool EDGE>
__device__ __forceinline__ void walk(const float* __restrict__ p,
                                     float* __restrict__ op,
                                     bool v0, bool v1, bool v2, bool v3,
                                     int nwarm, int nmain, int nepi,
                                     const ull (&nw)[4][4]) {
    float2 q0a, q0b, q0c, q1a, q1b, q2a;
    q0a = q0b = q0c = q1a = q1b = q2a = make_float2(BIGF, BIGF);
    float2 cd[4];
    ull r0, r1, r2, r3;

    // warmup columns (no output yet)
    for (int s = 0; s < nwarm; s++) {
        loadrows<EDGE>(p, v0, v1, v2, v3, r0, r1, r2, r3);
        colpass(r0, r1, r2, r3, nw, cd);
        q0a = q0b; q0b = q0c; q0c = cd[0];
        q1a = q1b; q1b = cd[1];
        q2a = cd[2];
        p += C;
    }

    // main: each step loads one column, emits one output
#pragma unroll 4
    for (int s = 0; s < nmain; s++) {
        loadrows<EDGE>(p, v0, v1, v2, v3, r0, r1, r2, r3);
        colpass(r0, r1, r2, r3, nw, cd);
        float ox = fminf(fminf(q0a.x, q1a.x), fminf(q2a.x, cd[3].x));
        float oy = fminf(fminf(q0a.y, q1a.y), fminf(q2a.y, cd[3].y));
        *(float2*)op = make_float2(ox, oy);
        q0a = q0b; q0b = q0c; q0c = cd[0];
        q1a = q1b; q1b = cd[1];
        q2a = cd[2];
        p += C; op += C;
    }

    // epilogue: right image edge — remaining outputs use BIG columns
    for (int s = 0; s < nepi; s++) {
        colpass(BIG2, BIG2, BIG2, BIG2, nw, cd);
        float ox = fminf(fminf(q0a.x, q1a.x), fminf(q2a.x, cd[3].x));
        float oy = fminf(fminf(q0a.y, q1a.y), fminf(q2a.y, cd[3].y));
        *(float2*)op = make_float2(ox, oy);
        q0a = q0b; q0b = q0c; q0c = cd[0];
        q1a = q1b; q1b = cd[1];
        q2a = cd[2];
        op += C;
    }
}

__global__ __launch_bounds__(THREADS, 3)
void erosion2d_kernel(const float* __restrict__ xin,
                      const float* __restrict__ wt,
                      float* __restrict__ out) {
    const int xbi = blockIdx.x;           // 0..W/XW-1
    const int by  = blockIdx.y;           // 0..H/TY-1
    const int b   = blockIdx.z;
    const int tid = threadIdx.x;
    const int cp  = tid & 15;             // channel pair 0..15
    const int row = tid >> 4;             // 0..TY-1
    const int c0  = cp * 2;
    const int y   = by * TY + row;        // output row
    const int x0  = xbi * XW;             // first output column

    // negated, reflected weights packed as f32x2
    ull nw[4][4];
#pragma unroll
    for (int d = 0; d < 4; d++)
#pragma unroll
        for (int k = 0; k < 4; k++) {
            const float* wp = wt + ((3 - k) * 4 + (3 - d)) * C + c0;
            nw[d][k] = f2u(-wp[0], -wp[1]);
        }

    const bool v0 = (y - 1) >= 0;     // input row y-1
    const bool v1 = true;             // input row y   (always in range)
    const bool v2 = (y + 1) < H;
    const bool v3 = (y + 2) < H;

    const int cbeg  = (x0 == 0) ? 0 : x0 - 1;
    const int nwarm = (x0 == 0) ? 2 : 3;
    const int cend  = min(x0 + XW + 1, W - 1);   // last real column loaded
    const int nmain = cend - (x0 + 2) + 1;       // cols x0+2 .. cend, emit col-2
    const int nepi  = (x0 + XW + 1) - cend;      // 0 (interior) or 2 (right edge)

    const float* xbp = xin + (size_t)b * H * W * C;
    const float* p = xbp + ((ptrdiff_t)(y - 1) * W + cbeg) * C + c0;
    float* op = out + (((size_t)(b * H + y) * W) + x0) * C + c0;

    if (v0 & v2 & v3)
        walk<false>(p, op, v0, v1, v2, v3, nwarm, nmain, nepi, nw);
    else
        walk<true>(p, op, v0, v1, v2, v3, nwarm, nmain, nepi, nw);
}

extern "C" void kernel_launch(void* const* d_in, const int* in_sizes, int n_in,
                              void* d_out, int out_size) {
    const float* x = (const float*)d_in[0];
    const float* w = (const float*)d_in[1];
    float* out = (float*)d_out;

    dim3 grid(W / XW, H / TY, B);    // 4 x 32 x 8 = 1024 blocks
    erosion2d_kernel<<<grid, THREADS>>>(x, w, out);
}

// round 6
// speedup vs baseline: 1.7178x; 1.7178x over previous
#include <cuda_runtime.h>

// Erosion2D: out[b,y,x,c] = min_{dy,dx in [0,4)} x[y+dy-1, x+dx-1, c] - w[3-dy, 3-dx, c]
// Smem-tiled (R1 structure) with smaller 16x16 tile -> 3 blocks/SM (37.5% occ).
// Packed add.rn.f32x2 with pre-negated weights; 3-deep register ring over columns.

typedef unsigned long long ull;
#define BIGF 1e30f

constexpr int B = 8, H = 512, W = 512, C = 32;
constexpr int TY = 16, TX = 16;
constexpr int SR = TY + 3;                 // 19 smem rows
constexpr int SP = TX + 3;                 // 19 smem pixel-columns
constexpr int SMEM_FLOATS = SR * SP * C;   // 11552 floats = 46208 B (< 48K, no opt-in)
constexpr int THREADS = 256;

__device__ __forceinline__ ull addx2(ull a, ull b) {
    ull r; asm("add.rn.f32x2 %0, %1, %2;" : "=l"(r) : "l"(a), "l"(b)); return r;
}
__device__ __forceinline__ float2 u2f(ull a) {
    float2 f; asm("mov.b64 {%0, %1}, %2;" : "=f"(f.x), "=f"(f.y) : "l"(a)); return f;
}
__device__ __forceinline__ ull f2u(float x, float y) {
    ull r; asm("mov.b64 %0, {%1, %2};" : "=l"(r) : "f"(x), "f"(y)); return r;
}

__global__ __launch_bounds__(THREADS, 3)
void erosion2d_kernel(const float* __restrict__ xin,
                      const float* __restrict__ wt,
                      float* __restrict__ out) {
    __shared__ float tile[SMEM_FLOATS];

    const int bx = blockIdx.x;          // x tile: 0..31
    const int by = blockIdx.y;          // y tile: 0..31
    const int b  = blockIdx.z;          // batch
    const int x0 = bx * TX;
    const int y0 = by * TY;
    const int tid = threadIdx.x;

    const float* xb = xin + (size_t)b * H * W * C;

    // ---------------- load halo tile into smem ----------------
    const bool interior = (bx > 0) & (bx < (W / TX - 1)) & (by > 0) & (by < (H / TY - 1));
    constexpr int LOADS = SR * SP * (C / 4);   // float4 loads: 2888

    if (interior) {
        #pragma unroll 4
        for (int i = tid; i < LOADS; i += THREADS) {
            int r   = i / (SP * (C / 4));
            int rem = i - r * (SP * (C / 4));
            int p   = rem >> 3;            // pixel in row (C/4 == 8)
            int q   = rem & 7;             // channel quad
            int gy = y0 - 1 + r;
            int gx = x0 - 1 + p;
            float4 v = *(const float4*)(xb + ((size_t)gy * W + gx) * C + q * 4);
            *(float4*)(tile + (r * SP + p) * C + q * 4) = v;
        }
    } else {
        #pragma unroll 4
        for (int i = tid; i < LOADS; i += THREADS) {
            int r   = i / (SP * (C / 4));
            int rem = i - r * (SP * (C / 4));
            int p   = rem >> 3;
            int q   = rem & 7;
            int gy = y0 - 1 + r;
            int gx = x0 - 1 + p;
            float4 v;
            if (gy >= 0 && gy < H && gx >= 0 && gx < W) {
                v = *(const float4*)(xb + ((size_t)gy * W + gx) * C + q * 4);
            } else {
                v = make_float4(BIGF, BIGF, BIGF, BIGF);
            }
            *(float4*)(tile + (r * SP + p) * C + q * 4) = v;
        }
    }

    // ---------------- weights (overlap with staging) ----------------
    const int cp = tid & 15;        // channel pair: channels 2*cp, 2*cp+1
    const int ty = tid >> 4;        // output row in tile: 0..15
    const int c0 = cp * 2;

    // negated reflected weights: nw[d][k] = -w[3-k][3-d][c0..c0+1]
    ull nw[4][4];
    #pragma unroll
    for (int d = 0; d < 4; d++) {
        #pragma unroll
        for (int k = 0; k < 4; k++) {
            const float* wp = wt + ((3 - k) * 4 + (3 - d)) * C + c0;
            nw[d][k] = f2u(-wp[0], -wp[1]);
        }
    }

    __syncthreads();

    // ---------------- compute ----------------
    float* op = out + (((size_t)(b * H + y0 + ty) * W + x0) * C) + c0;

    // ring: q0a=c0(s-3) q0b=c0(s-2) q0c=c0(s-1); q1a=c1(s-2) q1b=c1(s-1); q2a=c2(s-1)
    float2 q0a, q0b, q0c, q1a, q1b, q2a;
    q0a = q0b = q0c = q1a = q1b = q2a = make_float2(BIGF, BIGF);

    const int rowbase = ty * SP;

    #pragma unroll
    for (int s = 0; s < SP; s++) {
        // 4 input rows of smem column s (this thread's channel pair)
        ull r0 = *(const ull*)(tile + ((rowbase) + s) * C + c0);
        ull r1 = *(const ull*)(tile + ((rowbase + SP) + s) * C + c0);
        ull r2 = *(const ull*)(tile + ((rowbase + 2 * SP) + s) * C + c0);
        ull r3 = *(const ull*)(tile + ((rowbase + 3 * SP) + s) * C + c0);

        // column pass: cd[d] = min_k (r_k + nw[d][k])
        float2 cd[4];
        #pragma unroll
        for (int d = 0; d < 4; d++) {
            float2 a0 = u2f(addx2(r0, nw[d][0]));
            float2 a1 = u2f(addx2(r1, nw[d][1]));
            float2 a2 = u2f(addx2(r2, nw[d][2]));
            float2 a3 = u2f(addx2(r3, nw[d][3]));
            cd[d].x = fminf(fminf(a0.x, a1.x), fminf(a2.x, a3.x));
            cd[d].y = fminf(fminf(a0.y, a1.y), fminf(a2.y, a3.y));
        }

        // horizontal combine: out(j=s-3) = min(c0(j), c1(j+1), c2(j+2), c3(j+3))
        if (s >= 3) {
            float ox = fminf(fminf(q0a.x, q1a.x), fminf(q2a.x, cd[3].x));
            float oy = fminf(fminf(q0a.y, q1a.y), fminf(q2a.y, cd[3].y));
            *(ull*)(op + (size_t)(s - 3) * C) = f2u(ox, oy);
        }

        // shift rings
        q0a = q0b; q0b = q0c; q0c = cd[0];
        q1a = q1b; q1b = cd[1];
        q2a = cd[2];
    }
}

extern "C" void kernel_launch(void* const* d_in, const int* in_sizes, int n_in,
                              void* d_out, int out_size) {
    const float* x = (const float*)d_in[0];
    const float* w = (const float*)d_in[1];
    float* out = (float*)d_out;

    dim3 grid(W / TX, H / TY, B);   // 32 x 32 x 8 = 8192 blocks
    erosion2d_kernel<<<grid, THREADS>>>(x, w, out);
}

// round 10
// speedup vs baseline: 2.2916x; 1.3340x over previous
#include <cuda_runtime.h>
#include <cuda_fp16.h>

// Erosion2D: out[b,y,x,c] = min_{dy,dx in [0,4)} x[y+dy-1, x+dx-1, c] - w[3-dy, 3-dx, c]
// fp16x2 compute version: smem tile staged as half2 (2 channels/reg), subtraction via
// __hadd2 with pre-negated half2 weights, mins via packed __hmin2. fp32 in/out.
// Border padding 1e30f -> +inf in fp16; min() never selects it for valid outputs.

#define BIGF 1e30f

constexpr int B = 8, H = 512, W = 512, C = 32;
constexpr int TY = 16, TX = 16;
constexpr int SR = TY + 3;                 // 19 smem rows
constexpr int SP = TX + 3;                 // 19 smem pixel-columns
constexpr int PIX_H2 = C / 2;              // 16 half2 per pixel
constexpr int SMEM_H2 = SR * SP * PIX_H2;  // 5776 half2 = 23104 B
constexpr int THREADS = 256;

__device__ __forceinline__ unsigned h2u(__half2 h) {
    return reinterpret_cast<unsigned&>(h);
}

__global__ __launch_bounds__(THREADS, 4)
void erosion2d_kernel(const float* __restrict__ xin,
                      const float* __restrict__ wt,
                      float* __restrict__ out) {
    __shared__ __half2 tile[SMEM_H2];

    const int bx = blockIdx.x;          // x tile: 0..31
    const int by = blockIdx.y;          // y tile: 0..31
    const int b  = blockIdx.z;          // batch
    const int x0 = bx * TX;
    const int y0 = by * TY;
    const int tid = threadIdx.x;

    const float* xb = xin + (size_t)b * H * W * C;

    // ---------------- load halo tile into smem (fp32 -> fp16x2) ----------------
    const bool interior = (bx > 0) & (bx < (W / TX - 1)) & (by > 0) & (by < (H / TY - 1));
    constexpr int LOADS = SR * SP * (C / 4);   // float4 loads: 2888

    if (interior) {
        #pragma unroll 4
        for (int i = tid; i < LOADS; i += THREADS) {
            int r   = i / (SP * (C / 4));
            int rem = i - r * (SP * (C / 4));
            int p   = rem >> 3;            // pixel in row (C/4 == 8)
            int q   = rem & 7;             // channel quad
            int gy = y0 - 1 + r;
            int gx = x0 - 1 + p;
            float4 v = *(const float4*)(xb + ((size_t)gy * W + gx) * C + q * 4);
            __half2 h01 = __floats2half2_rn(v.x, v.y);
            __half2 h23 = __floats2half2_rn(v.z, v.w);
            int hi = (r * SP + p) * PIX_H2 + q * 2;
            *(uint2*)(tile + hi) = make_uint2(h2u(h01), h2u(h23));
        }
    } else {
        #pragma unroll 4
        for (int i = tid; i < LOADS; i += THREADS) {
            int r   = i / (SP * (C / 4));
            int rem = i - r * (SP * (C / 4));
            int p   = rem >> 3;
            int q   = rem & 7;
            int gy = y0 - 1 + r;
            int gx = x0 - 1 + p;
            float4 v;
            if (gy >= 0 && gy < H && gx >= 0 && gx < W) {
                v = *(const float4*)(xb + ((size_t)gy * W + gx) * C + q * 4);
            } else {
                v = make_float4(BIGF, BIGF, BIGF, BIGF);   // -> +inf in fp16
            }
            __half2 h01 = __floats2half2_rn(v.x, v.y);
            __half2 h23 = __floats2half2_rn(v.z, v.w);
            int hi = (r * SP + p) * PIX_H2 + q * 2;
            *(uint2*)(tile + hi) = make_uint2(h2u(h01), h2u(h23));
        }
    }

    // ---------------- weights (overlap with staging) ----------------
    const int cp = tid & 15;        // channel pair: channels 2*cp, 2*cp+1
    const int ty = tid >> 4;        // output row in tile: 0..15
    const int c0 = cp * 2;

    // negated reflected weights: nw[d][k] = -w[3-k][3-d][c0..c0+1] as half2
    __half2 nw[4][4];
    #pragma unroll
    for (int d = 0; d < 4; d++) {
        #pragma unroll
        for (int k = 0; k < 4; k++) {
            const float* wp = wt + ((3 - k) * 4 + (3 - d)) * C + c0;
            nw[d][k] = __floats2half2_rn(-wp[0], -wp[1]);
        }
    }

    __syncthreads();

    // ---------------- compute ----------------
    float* op = out + (((size_t)(b * H + y0 + ty) * W + x0) * C) + c0;

    // ring: q0a=c0(s-3) q0b=c0(s-2) q0c=c0(s-1); q1a=c1(s-2) q1b=c1(s-1); q2a=c2(s-1)
    const __half2 BIGH = __floats2half2_rn(BIGF, BIGF);   // +inf pair
    __half2 q0a = BIGH, q0b = BIGH, q0c = BIGH, q1a = BIGH, q1b = BIGH, q2a = BIGH;

    const int rowbase = ty * SP;

    #pragma unroll
    for (int s = 0; s < SP; s++) {
        // 4 input rows of smem column s (this thread's channel pair)
        __half2 r0 = tile[((rowbase) + s) * PIX_H2 + cp];
        __half2 r1 = tile[((rowbase + SP) + s) * PIX_H2 + cp];
        __half2 r2 = tile[((rowbase + 2 * SP) + s) * PIX_H2 + cp];
        __half2 r3 = tile[((rowbase + 3 * SP) + s) * PIX_H2 + cp];

        // column pass: cd[d] = min_k (r_k + nw[d][k])   (packed over 2 channels)
        __half2 cd[4];
        #pragma unroll
        for (int d = 0; d < 4; d++) {
            __half2 a0 = __hadd2(r0, nw[d][0]);
            __half2 a1 = __hadd2(r1, nw[d][1]);
            __half2 a2 = __hadd2(r2, nw[d][2]);
            __half2 a3 = __hadd2(r3, nw[d][3]);
            cd[d] = __hmin2(__hmin2(a0, a1), __hmin2(a2, a3));
        }

        // horizontal combine: out(j=s-3) = min(c0(j), c1(j+1), c2(j+2), c3(j+3))
        if (s >= 3) {
            __half2 o = __hmin2(__hmin2(q0a, q1a), __hmin2(q2a, cd[3]));
            float2 of = __half22float2(o);
            *(float2*)(op + (size_t)(s - 3) * C) = of;
        }

        // shift rings
        q0a = q0b; q0b = q0c; q0c = cd[0];
        q1a = q1b; q1b = cd[1];
        q2a = cd[2];
    }
}

extern "C" void kernel_launch(void* const* d_in, const int* in_sizes, int n_in,
                              void* d_out, int out_size) {
    const float* x = (const float*)d_in[0];
    const float* w = (const float*)d_in[1];
    float* out = (float*)d_out;

    dim3 grid(W / TX, H / TY, B);   // 32 x 32 x 8 = 8192 blocks
    erosion2d_kernel<<<grid, THREADS>>>(x, w, out);
}